// round 10
// baseline (speedup 1.0000x reference)
#include <cuda_runtime.h>
#include <cuda_bf16.h>
#include <math.h>
#include <stdint.h>

#define N_LEVELS 16
#define TBL (1u << 19)
#define BLOCK 128
#define ASTRIDE 68   // 64 + 4 pad floats: conflict-free fragment access

struct Meta {
    float scale[N_LEVELS];
    int   res[N_LEVELS];
    unsigned hashed_mask;
};

// Fragment-packed weights: wp[(kt*8+nt)*32 + lane] = {hi(k0,n), lo(k0,n), hi(k1,n), lo(k1,n)}
// where lane=(g<<2)|tig, k0=kt*8+tig, k1=k0+4, n=nt*8+g.  One coalesced LDG.128/fragment.
__device__ float4 g_w1p[4 * 8 * 32];
__device__ float4 g_w2p[8 * 8 * 32];
__device__ float4 g_w3p[8 * 8 * 32];

static __device__ __forceinline__ float tf32r(float x) {
    uint32_t r;
    asm("cvt.rna.tf32.f32 %0, %1;" : "=r"(r) : "f"(x));
    return __uint_as_float(r);
}

static __device__ __forceinline__ float sp10(float v) {
    float t = 10.0f * v;
    float e = __expf(-fabsf(t));
    return (__logf(1.0f + e) + fmaxf(t, 0.0f)) * 0.1f;
}

static __device__ __forceinline__ void mma8(float* d, const uint32_t* a,
                                            uint32_t b0, uint32_t b1) {
    asm volatile(
        "mma.sync.aligned.m16n8k8.row.col.f32.tf32.tf32.f32 "
        "{%0,%1,%2,%3}, {%4,%5,%6,%7}, {%8,%9}, {%0,%1,%2,%3};"
        : "+f"(d[0]), "+f"(d[1]), "+f"(d[2]), "+f"(d[3])
        : "r"(a[0]), "r"(a[1]), "r"(a[2]), "r"(a[3]), "r"(b0), "r"(b1));
}

template <int K>
static __device__ void pack_layer(const float* __restrict__ W, float4* __restrict__ wp,
                                  int tid, int stride) {
    const int KT = K / 8;
    for (int idx = tid; idx < KT * 8 * 32; idx += stride) {
        int kt = idx >> 8;            // /(8*32)
        int nt = (idx >> 5) & 7;
        int lane = idx & 31;
        int g = lane >> 2, tig = lane & 3;
        int k0 = kt * 8 + tig, k1 = k0 + 4;
        int n = nt * 8 + g;
        float wa = W[n * K + k0], wb = W[n * K + k1];
        float ha = tf32r(wa), hb = tf32r(wb);
        wp[idx] = make_float4(ha, tf32r(wa - ha), hb, tf32r(wb - hb));
    }
}

__global__ void prep_weights(const float* __restrict__ W1,
                             const float* __restrict__ W2,
                             const float* __restrict__ W3)
{
    const int tid = blockIdx.x * blockDim.x + threadIdx.x;
    const int stride = gridDim.x * blockDim.x;
    pack_layer<32>(W1, g_w1p, tid, stride);
    pack_layer<64>(W2, g_w2p, tid, stride);
    pack_layer<64>(W3, g_w3p, tid, stride);
}

// One layer GEMM: acc[2][8][4] += act[32pts x KT*8] @ W.  Warp-collective.
template <int KT>
static __device__ __forceinline__ void layer_gemm(const float* __restrict__ act,
                                                  const float4* __restrict__ wp,
                                                  int mbase, int g, int tig, int lane,
                                                  float acc[2][8][4])
{
#pragma unroll
    for (int m = 0; m < 2; m++)
#pragma unroll
        for (int nt = 0; nt < 8; nt++)
#pragma unroll
            for (int c = 0; c < 4; c++) acc[m][nt][c] = 0.0f;

#pragma unroll
    for (int kt = 0; kt < KT; kt++) {
        uint32_t ahi[2][4], alo[2][4];
#pragma unroll
        for (int m = 0; m < 2; m++) {
            const int r0 = mbase + m * 16 + g;
#pragma unroll
            for (int r = 0; r < 4; r++) {
                const int row = r0 + (r & 1) * 8;
                const int col = kt * 8 + tig + (r >> 1) * 4;
                float a = act[row * ASTRIDE + col];
                float h = tf32r(a);
                ahi[m][r] = __float_as_uint(h);
                alo[m][r] = __float_as_uint(tf32r(a - h));
            }
        }
        const float4* wrow = wp + kt * 8 * 32 + lane;
#pragma unroll
        for (int nt = 0; nt < 8; nt++) {
            float4 w = __ldg(&wrow[nt * 32]);
            uint32_t bh0 = __float_as_uint(w.x), bl0 = __float_as_uint(w.y);
            uint32_t bh1 = __float_as_uint(w.z), bl1 = __float_as_uint(w.w);
#pragma unroll
            for (int m = 0; m < 2; m++) {
                mma8(acc[m][nt], ahi[m], bh0, bh1);
                mma8(acc[m][nt], ahi[m], bl0, bl1);
                mma8(acc[m][nt], alo[m], bh0, bh1);
            }
        }
    }
}

static __device__ __forceinline__ void layer_store(float* __restrict__ act,
                                                   int mbase, int g, int tig,
                                                   const float acc[2][8][4])
{
#pragma unroll
    for (int m = 0; m < 2; m++) {
        const int r0 = mbase + m * 16 + g;
#pragma unroll
        for (int nt = 0; nt < 8; nt++) {
            const int col = nt * 8 + 2 * tig;
            *(float2*)(act + r0 * ASTRIDE + col) =
                make_float2(sp10(acc[m][nt][0]), sp10(acc[m][nt][1]));
            *(float2*)(act + (r0 + 8) * ASTRIDE + col) =
                make_float2(sp10(acc[m][nt][2]), sp10(acc[m][nt][3]));
        }
    }
}

__global__ void __launch_bounds__(BLOCK)
sdf_kernel(const float* __restrict__ x,
           const float* __restrict__ grid,
           const float* __restrict__ W4,
           float* __restrict__ out,
           int N, Meta meta)
{
    __shared__ float act[BLOCK * ASTRIDE];

    const int tid = threadIdx.x;
    const int p = blockIdx.x * BLOCK + tid;

    // ---- Encoding with x-pair fused gathers ----
    if (p < N) {
        const float px = x[p * 3 + 0];
        const float py = x[p * 3 + 1];
        const float pz = x[p * 3 + 2];

        for (int l = 0; l < N_LEVELS; l++) {
            const float s = meta.scale[l];
            const int res = meta.res[l];
            const bool hashed = (meta.hashed_mask >> l) & 1u;

            float fx = fmaf(px, s, 0.5f);
            float fy = fmaf(py, s, 0.5f);
            float fz = fmaf(pz, s, 0.5f);
            float fx0 = floorf(fx), fy0 = floorf(fy), fz0 = floorf(fz);
            float rx = fx - fx0, ry = fy - fy0, rz = fz - fz0;
            int ix = (int)fx0, iy = (int)fy0, iz = (int)fz0;

            const float2* g = (const float2*)grid + (size_t)l * TBL;
            float a0 = 0.0f, a1 = 0.0f;

#pragma unroll
            for (int cyz = 0; cyz < 4; cyz++) {
                const int cy = cyz & 1, cz = cyz >> 1;
                const float wyz = (cy ? ry : 1.0f - ry) * (cz ? rz : 1.0f - rz);
                const float w0 = wyz * (1.0f - rx);
                const float w1 = wyz * rx;

                unsigned i0, i1;
                if (hashed) {
                    unsigned gx = (unsigned)ix;
                    unsigned hyz = ((unsigned)(iy + cy) * 2654435761u) ^
                                   ((unsigned)(iz + cz) * 805459861u);
                    i0 = (gx ^ hyz) & (TBL - 1u);
                    i1 = ((gx + 1u) ^ hyz) & (TBL - 1u);
                } else {
                    int gy = min(max(iy + cy, 0), res - 1);
                    int gz = min(max(iz + cz, 0), res - 1);
                    int gx0 = min(max(ix, 0), res - 1);
                    int gx1 = min(max(ix + 1, 0), res - 1);
                    unsigned byz = (unsigned)(res * (gy + res * gz));
                    i0 = (unsigned)gx0 + byz;
                    i1 = (unsigned)gx1 + byz;
                }

                float2 f0, f1;
                if ((i0 ^ i1) == 1u) {
                    // aligned 16B pair {2m, 2m+1}: one LDG.128, one L1 line
                    float4 v = __ldg((const float4*)(g + (i0 & ~1u)));
                    if (i0 & 1u) { f0 = make_float2(v.z, v.w); f1 = make_float2(v.x, v.y); }
                    else         { f0 = make_float2(v.x, v.y); f1 = make_float2(v.z, v.w); }
                } else {
                    f0 = __ldg(&g[i0]);
                    f1 = __ldg(&g[i1]);
                }
                a0 = fmaf(w0, f0.x, fmaf(w1, f1.x, a0));
                a1 = fmaf(w0, f0.y, fmaf(w1, f1.y, a1));
            }
            *(float2*)(act + tid * ASTRIDE + 2 * l) = make_float2(a0, a1);
        }
    } else {
#pragma unroll
        for (int l = 0; l < N_LEVELS; l++)
            *(float2*)(act + tid * ASTRIDE + 2 * l) = make_float2(0.0f, 0.0f);
    }
    __syncwarp();

    // ---- MLP ----
    const int lane  = tid & 31;
    const int g     = lane >> 2;
    const int tig   = lane & 3;
    const int mbase = (tid >> 5) * 32;

    float acc[2][8][4];

    layer_gemm<4>(act, g_w1p, mbase, g, tig, lane, acc);
    layer_store(act, mbase, g, tig, acc);
    __syncwarp();

    layer_gemm<8>(act, g_w2p, mbase, g, tig, lane, acc);
    layer_store(act, mbase, g, tig, acc);
    __syncwarp();

    layer_gemm<8>(act, g_w3p, mbase, g, tig, lane, acc);

    // ---- Output layer ----
    float part[4] = {0.0f, 0.0f, 0.0f, 0.0f};
#pragma unroll
    for (int m = 0; m < 2; m++) {
#pragma unroll
        for (int nt = 0; nt < 8; nt++) {
            const int j = nt * 8 + 2 * tig;
            float w4a = __ldg(&W4[j]);
            float w4b = __ldg(&W4[j + 1]);
            part[m * 2 + 0] = fmaf(sp10(acc[m][nt][0]), w4a,
                             fmaf(sp10(acc[m][nt][1]), w4b, part[m * 2 + 0]));
            part[m * 2 + 1] = fmaf(sp10(acc[m][nt][2]), w4a,
                             fmaf(sp10(acc[m][nt][3]), w4b, part[m * 2 + 1]));
        }
    }
#pragma unroll
    for (int d = 0; d < 4; d++) {
        part[d] += __shfl_xor_sync(0xffffffffu, part[d], 1);
        part[d] += __shfl_xor_sync(0xffffffffu, part[d], 2);
    }
    if (tig == 0) {
        const int base = blockIdx.x * BLOCK + mbase;
#pragma unroll
        for (int m = 0; m < 2; m++) {
            int p0 = base + m * 16 + g;
            if (p0 < N) out[p0] = part[m * 2 + 0];
            if (p0 + 8 < N) out[p0 + 8] = part[m * 2 + 1];
        }
    }
}

extern "C" void kernel_launch(void* const* d_in, const int* in_sizes, int n_in,
                              void* d_out, int out_size)
{
    const float* x    = (const float*)d_in[0];
    const float* grid = (const float*)d_in[1];
    const float* W1   = (const float*)d_in[2];
    const float* W2   = (const float*)d_in[3];
    const float* W3   = (const float*)d_in[4];
    const float* W4   = (const float*)d_in[5];
    float* out = (float*)d_out;

    const int N = in_sizes[0] / 3;

    Meta meta;
    const double Bv = pow(2.0, log2(2048.0 / 16.0) / (double)(N_LEVELS - 1));
    unsigned mask = 0;
    for (int l = 0; l < N_LEVELS; l++) {
        double sc = 16.0 * pow(Bv, (double)l) - 1.0;
        int res = (int)ceil(sc) + 1;
        meta.scale[l] = (float)sc;
        meta.res[l] = res;
        if ((long long)res * res * res > (long long)TBL) mask |= (1u << l);
    }
    meta.hashed_mask = mask;

    prep_weights<<<16, 256>>>(W1, W2, W3);

    const int blocks = (N + BLOCK - 1) / BLOCK;
    sdf_kernel<<<blocks, BLOCK>>>(x, grid, W4, out, N, meta);
}

// round 11
// speedup vs baseline: 1.0084x; 1.0084x over previous
#include <cuda_runtime.h>
#include <cuda_bf16.h>
#include <math.h>
#include <stdint.h>

#define N_LEVELS 16
#define TBL (1u << 19)
#define NTHREADS 256
#define POINTS 128
#define ASTRIDE 68   // 64 + 4 pad floats: conflict-free fragment access

struct Meta {
    float scale[N_LEVELS];
    int   res[N_LEVELS];
    unsigned hashed_mask;
};

// Fragment-packed weights: wp[(kt*8+nt)*32 + lane] = {hi(k0,n), lo(k0,n), hi(k1,n), lo(k1,n)}
// lane=(g<<2)|tig, k0=kt*8+tig, k1=k0+4, n=nt*8+g.  One coalesced LDG.128/fragment.
__device__ float4 g_w1p[4 * 8 * 32];
__device__ float4 g_w2p[8 * 8 * 32];
__device__ float4 g_w3p[8 * 8 * 32];

static __device__ __forceinline__ float tf32r(float x) {
    uint32_t r;
    asm("cvt.rna.tf32.f32 %0, %1;" : "=r"(r) : "f"(x));
    return __uint_as_float(r);
}

static __device__ __forceinline__ float sp10(float v) {
    float t = 10.0f * v;
    float e = __expf(-fabsf(t));
    return (__logf(1.0f + e) + fmaxf(t, 0.0f)) * 0.1f;
}

static __device__ __forceinline__ void mma8(float* d, const uint32_t* a,
                                            uint32_t b0, uint32_t b1) {
    asm volatile(
        "mma.sync.aligned.m16n8k8.row.col.f32.tf32.tf32.f32 "
        "{%0,%1,%2,%3}, {%4,%5,%6,%7}, {%8,%9}, {%0,%1,%2,%3};"
        : "+f"(d[0]), "+f"(d[1]), "+f"(d[2]), "+f"(d[3])
        : "r"(a[0]), "r"(a[1]), "r"(a[2]), "r"(a[3]), "r"(b0), "r"(b1));
}

template <int K>
static __device__ void pack_layer(const float* __restrict__ W, float4* __restrict__ wp,
                                  int tid, int stride) {
    const int KT = K / 8;
    for (int idx = tid; idx < KT * 8 * 32; idx += stride) {
        int kt = idx >> 8;
        int nt = (idx >> 5) & 7;
        int lane = idx & 31;
        int g = lane >> 2, tig = lane & 3;
        int k0 = kt * 8 + tig, k1 = k0 + 4;
        int n = nt * 8 + g;
        float wa = W[n * K + k0], wb = W[n * K + k1];
        float ha = tf32r(wa), hb = tf32r(wb);
        wp[idx] = make_float4(ha, tf32r(wa - ha), hb, tf32r(wb - hb));
    }
}

__global__ void prep_weights(const float* __restrict__ W1,
                             const float* __restrict__ W2,
                             const float* __restrict__ W3)
{
    const int tid = blockIdx.x * blockDim.x + threadIdx.x;
    const int stride = gridDim.x * blockDim.x;
    pack_layer<32>(W1, g_w1p, tid, stride);
    pack_layer<64>(W2, g_w2p, tid, stride);
    pack_layer<64>(W3, g_w3p, tid, stride);
}

// One layer GEMM: acc[8][4] += act[16pts x KT*8] @ W.  Warp-collective, 16-row m-tile.
template <int KT>
static __device__ __forceinline__ void layer_gemm(const float* __restrict__ act,
                                                  const float4* __restrict__ wp,
                                                  int mbase, int g, int tig, int lane,
                                                  float acc[8][4])
{
#pragma unroll
    for (int nt = 0; nt < 8; nt++)
#pragma unroll
        for (int c = 0; c < 4; c++) acc[nt][c] = 0.0f;

#pragma unroll
    for (int kt = 0; kt < KT; kt++) {
        uint32_t ahi[4], alo[4];
        const int r0 = mbase + g;
#pragma unroll
        for (int r = 0; r < 4; r++) {
            const int row = r0 + (r & 1) * 8;
            const int col = kt * 8 + tig + (r >> 1) * 4;
            float a = act[row * ASTRIDE + col];
            float h = tf32r(a);
            ahi[r] = __float_as_uint(h);
            alo[r] = __float_as_uint(tf32r(a - h));
        }
        const float4* wrow = wp + kt * 8 * 32 + lane;
#pragma unroll
        for (int nt = 0; nt < 8; nt++) {
            float4 w = __ldg(&wrow[nt * 32]);
            uint32_t bh0 = __float_as_uint(w.x), bl0 = __float_as_uint(w.y);
            uint32_t bh1 = __float_as_uint(w.z), bl1 = __float_as_uint(w.w);
            mma8(acc[nt], ahi, bh0, bh1);
            mma8(acc[nt], ahi, bl0, bl1);
            mma8(acc[nt], alo, bh0, bh1);
        }
    }
}

static __device__ __forceinline__ void layer_store(float* __restrict__ act,
                                                   int mbase, int g, int tig,
                                                   const float acc[8][4])
{
    const int r0 = mbase + g;
#pragma unroll
    for (int nt = 0; nt < 8; nt++) {
        const int col = nt * 8 + 2 * tig;
        *(float2*)(act + r0 * ASTRIDE + col) =
            make_float2(sp10(acc[nt][0]), sp10(acc[nt][1]));
        *(float2*)(act + (r0 + 8) * ASTRIDE + col) =
            make_float2(sp10(acc[nt][2]), sp10(acc[nt][3]));
    }
}

__global__ void __launch_bounds__(NTHREADS, 3)
sdf_kernel(const float* __restrict__ x,
           const float* __restrict__ grid,
           const float* __restrict__ W4,
           float* __restrict__ out,
           int N, Meta meta)
{
    __shared__ float act[POINTS * ASTRIDE];

    const int tid = threadIdx.x;
    // Encoding: 2 threads per point; thread handles 8 levels.
    const int erow  = tid & (POINTS - 1);
    const int lbase = (tid >> 7) * 8;
    const int p = blockIdx.x * POINTS + erow;

    if (p < N) {
        const float px = x[p * 3 + 0];
        const float py = x[p * 3 + 1];
        const float pz = x[p * 3 + 2];

#pragma unroll
        for (int li = 0; li < 8; li++) {
            const int l = lbase + li;
            const float s = meta.scale[l];
            const int res = meta.res[l];
            const bool hashed = (meta.hashed_mask >> l) & 1u;

            float fx = fmaf(px, s, 0.5f);
            float fy = fmaf(py, s, 0.5f);
            float fz = fmaf(pz, s, 0.5f);
            float fx0 = floorf(fx), fy0 = floorf(fy), fz0 = floorf(fz);
            float rx = fx - fx0, ry = fy - fy0, rz = fz - fz0;
            int ix = (int)fx0, iy = (int)fy0, iz = (int)fz0;

            const float2* g = (const float2*)grid + (size_t)l * TBL;
            float a0 = 0.0f, a1 = 0.0f;

#pragma unroll
            for (int cyz = 0; cyz < 4; cyz++) {
                const int cy = cyz & 1, cz = cyz >> 1;
                const float wyz = (cy ? ry : 1.0f - ry) * (cz ? rz : 1.0f - rz);
                const float w0 = wyz * (1.0f - rx);
                const float w1 = wyz * rx;

                unsigned i0, i1;
                if (hashed) {
                    unsigned gx = (unsigned)ix;
                    unsigned hyz = ((unsigned)(iy + cy) * 2654435761u) ^
                                   ((unsigned)(iz + cz) * 805459861u);
                    i0 = (gx ^ hyz) & (TBL - 1u);
                    i1 = ((gx + 1u) ^ hyz) & (TBL - 1u);
                } else {
                    int gy = min(max(iy + cy, 0), res - 1);
                    int gz = min(max(iz + cz, 0), res - 1);
                    int gx0 = min(max(ix, 0), res - 1);
                    int gx1 = min(max(ix + 1, 0), res - 1);
                    unsigned byz = (unsigned)(res * (gy + res * gz));
                    i0 = (unsigned)gx0 + byz;
                    i1 = (unsigned)gx1 + byz;
                }

                float2 f0, f1;
                if ((i0 ^ i1) == 1u) {
                    float4 v = __ldg((const float4*)(g + (i0 & ~1u)));
                    if (i0 & 1u) { f0 = make_float2(v.z, v.w); f1 = make_float2(v.x, v.y); }
                    else         { f0 = make_float2(v.x, v.y); f1 = make_float2(v.z, v.w); }
                } else {
                    f0 = __ldg(&g[i0]);
                    f1 = __ldg(&g[i1]);
                }
                a0 = fmaf(w0, f0.x, fmaf(w1, f1.x, a0));
                a1 = fmaf(w0, f0.y, fmaf(w1, f1.y, a1));
            }
            *(float2*)(act + erow * ASTRIDE + 2 * l) = make_float2(a0, a1);
        }
    } else {
#pragma unroll
        for (int li = 0; li < 8; li++)
            *(float2*)(act + erow * ASTRIDE + 2 * (lbase + li)) = make_float2(0.0f, 0.0f);
    }
    __syncthreads();   // point rows are written by two warps

    // ---- MLP: 8 warps, each owns 16 points (one m16 tile), all 64 outputs ----
    const int lane  = tid & 31;
    const int g     = lane >> 2;
    const int tig   = lane & 3;
    const int warp  = tid >> 5;
    const int mbase = warp * 16;

    float acc[8][4];

    layer_gemm<4>(act, g_w1p, mbase, g, tig, lane, acc);
    layer_store(act, mbase, g, tig, acc);
    __syncwarp();

    layer_gemm<8>(act, g_w2p, mbase, g, tig, lane, acc);
    layer_store(act, mbase, g, tig, acc);
    __syncwarp();

    layer_gemm<8>(act, g_w3p, mbase, g, tig, lane, acc);

    // ---- Output layer: sdf = softplus(h) . W4, reduce over tig quad ----
    float part[2] = {0.0f, 0.0f};
#pragma unroll
    for (int nt = 0; nt < 8; nt++) {
        const int j = nt * 8 + 2 * tig;
        float w4a = __ldg(&W4[j]);
        float w4b = __ldg(&W4[j + 1]);
        part[0] = fmaf(sp10(acc[nt][0]), w4a, fmaf(sp10(acc[nt][1]), w4b, part[0]));
        part[1] = fmaf(sp10(acc[nt][2]), w4a, fmaf(sp10(acc[nt][3]), w4b, part[1]));
    }
#pragma unroll
    for (int d = 0; d < 2; d++) {
        part[d] += __shfl_xor_sync(0xffffffffu, part[d], 1);
        part[d] += __shfl_xor_sync(0xffffffffu, part[d], 2);
    }
    if (tig == 0) {
        const int p0 = blockIdx.x * POINTS + mbase + g;
        if (p0 < N) out[p0] = part[0];
        if (p0 + 8 < N) out[p0 + 8] = part[1];
    }
}

extern "C" void kernel_launch(void* const* d_in, const int* in_sizes, int n_in,
                              void* d_out, int out_size)
{
    const float* x    = (const float*)d_in[0];
    const float* grid = (const float*)d_in[1];
    const float* W1   = (const float*)d_in[2];
    const float* W2   = (const float*)d_in[3];
    const float* W3   = (const float*)d_in[4];
    const float* W4   = (const float*)d_in[5];
    float* out = (float*)d_out;

    const int N = in_sizes[0] / 3;

    Meta meta;
    const double Bv = pow(2.0, log2(2048.0 / 16.0) / (double)(N_LEVELS - 1));
    unsigned mask = 0;
    for (int l = 0; l < N_LEVELS; l++) {
        double sc = 16.0 * pow(Bv, (double)l) - 1.0;
        int res = (int)ceil(sc) + 1;
        meta.scale[l] = (float)sc;
        meta.res[l] = res;
        if ((long long)res * res * res > (long long)TBL) mask |= (1u << l);
    }
    meta.hashed_mask = mask;

    prep_weights<<<16, 256>>>(W1, W2, W3);

    const int blocks = (N + POINTS - 1) / POINTS;
    sdf_kernel<<<blocks, NTHREADS>>>(x, grid, W4, out, N, meta);
}

// round 12
// speedup vs baseline: 1.5584x; 1.5455x over previous
#include <cuda_runtime.h>
#include <cuda_bf16.h>
#include <math.h>
#include <stdint.h>

#define N_LEVELS 16
#define TBL (1u << 19)
#define NTHREADS 256
#define POINTS 128
#define ASTRIDE 68   // 64 + 4 pad floats: conflict-free fragment access

struct Meta {
    float scale[N_LEVELS];
    int   res[N_LEVELS];
    unsigned hashed_mask;
};

// Fragment-packed single-tf32 weights: wp[(kt*8+nt)*32 + lane] = {w(k0,n), w(k1,n)}
// lane=(g<<2)|tig, k0=kt*8+tig, k1=k0+4, n=nt*8+g.  One coalesced LDG.64/fragment.
__device__ float2 g_w1p[4 * 8 * 32];
__device__ float2 g_w2p[8 * 8 * 32];
__device__ float2 g_w3p[8 * 8 * 32];

static __device__ __forceinline__ float tf32r(float x) {
    uint32_t r;
    asm("cvt.rna.tf32.f32 %0, %1;" : "=r"(r) : "f"(x));
    return __uint_as_float(r);
}

static __device__ __forceinline__ float sp10(float v) {
    float t = 10.0f * v;
    float e = __expf(-fabsf(t));
    return (__logf(1.0f + e) + fmaxf(t, 0.0f)) * 0.1f;
}

static __device__ __forceinline__ void mma8(float* d, const uint32_t* a,
                                            uint32_t b0, uint32_t b1) {
    asm volatile(
        "mma.sync.aligned.m16n8k8.row.col.f32.tf32.tf32.f32 "
        "{%0,%1,%2,%3}, {%4,%5,%6,%7}, {%8,%9}, {%0,%1,%2,%3};"
        : "+f"(d[0]), "+f"(d[1]), "+f"(d[2]), "+f"(d[3])
        : "r"(a[0]), "r"(a[1]), "r"(a[2]), "r"(a[3]), "r"(b0), "r"(b1));
}

template <int K>
static __device__ void pack_layer(const float* __restrict__ W, float2* __restrict__ wp,
                                  int tid, int stride) {
    const int KT = K / 8;
    for (int idx = tid; idx < KT * 8 * 32; idx += stride) {
        int kt = idx >> 8;
        int nt = (idx >> 5) & 7;
        int lane = idx & 31;
        int g = lane >> 2, tig = lane & 3;
        int k0 = kt * 8 + tig, k1 = k0 + 4;
        int n = nt * 8 + g;
        wp[idx] = make_float2(tf32r(W[n * K + k0]), tf32r(W[n * K + k1]));
    }
}

__global__ void prep_weights(const float* __restrict__ W1,
                             const float* __restrict__ W2,
                             const float* __restrict__ W3)
{
    const int tid = blockIdx.x * blockDim.x + threadIdx.x;
    const int stride = gridDim.x * blockDim.x;
    pack_layer<32>(W1, g_w1p, tid, stride);
    pack_layer<64>(W2, g_w2p, tid, stride);
    pack_layer<64>(W3, g_w3p, tid, stride);
}

// One layer GEMM: acc[8][4] += act[16pts x KT*8] @ W.  Warp-collective, m16 tile.
template <int KT>
static __device__ __forceinline__ void layer_gemm(const float* __restrict__ act,
                                                  const float2* __restrict__ wp,
                                                  int mbase, int g, int tig, int lane,
                                                  float acc[8][4])
{
#pragma unroll
    for (int nt = 0; nt < 8; nt++)
#pragma unroll
        for (int c = 0; c < 4; c++) acc[nt][c] = 0.0f;

#pragma unroll
    for (int kt = 0; kt < KT; kt++) {
        uint32_t ahi[4];
        const int r0 = mbase + g;
#pragma unroll
        for (int r = 0; r < 4; r++) {
            const int row = r0 + (r & 1) * 8;
            const int col = kt * 8 + tig + (r >> 1) * 4;
            ahi[r] = __float_as_uint(tf32r(act[row * ASTRIDE + col]));
        }
        const float2* wrow = wp + kt * 8 * 32 + lane;
#pragma unroll
        for (int nt = 0; nt < 8; nt++) {
            float2 w = __ldg(&wrow[nt * 32]);
            mma8(acc[nt], ahi, __float_as_uint(w.x), __float_as_uint(w.y));
        }
    }
}

static __device__ __forceinline__ void layer_store(float* __restrict__ act,
                                                   int mbase, int g, int tig,
                                                   const float acc[8][4])
{
    const int r0 = mbase + g;
#pragma unroll
    for (int nt = 0; nt < 8; nt++) {
        const int col = nt * 8 + 2 * tig;
        *(float2*)(act + r0 * ASTRIDE + col) =
            make_float2(sp10(acc[nt][0]), sp10(acc[nt][1]));
        *(float2*)(act + (r0 + 8) * ASTRIDE + col) =
            make_float2(sp10(acc[nt][2]), sp10(acc[nt][3]));
    }
}

__global__ void __launch_bounds__(NTHREADS, 3)
sdf_kernel(const float* __restrict__ x,
           const float* __restrict__ grid,
           const float* __restrict__ W4,
           float* __restrict__ out,
           int N, Meta meta)
{
    __shared__ float act[POINTS * ASTRIDE];

    const int tid = threadIdx.x;
    // Encoding: 2 threads per point; thread handles 8 levels.
    const int erow  = tid & (POINTS - 1);
    const int lbase = (tid >> 7) * 8;
    const int p = blockIdx.x * POINTS + erow;

    if (p < N) {
        const float px = x[p * 3 + 0];
        const float py = x[p * 3 + 1];
        const float pz = x[p * 3 + 2];

#pragma unroll
        for (int li = 0; li < 8; li++) {
            const int l = lbase + li;
            const float s = meta.scale[l];
            const int res = meta.res[l];
            const bool hashed = (meta.hashed_mask >> l) & 1u;

            float fx = fmaf(px, s, 0.5f);
            float fy = fmaf(py, s, 0.5f);
            float fz = fmaf(pz, s, 0.5f);
            float fx0 = floorf(fx), fy0 = floorf(fy), fz0 = floorf(fz);
            float rx = fx - fx0, ry = fy - fy0, rz = fz - fz0;
            int ix = (int)fx0, iy = (int)fy0, iz = (int)fz0;

            const float2* g = (const float2*)grid + (size_t)l * TBL;
            float a0 = 0.0f, a1 = 0.0f;

#pragma unroll
            for (int cyz = 0; cyz < 4; cyz++) {
                const int cy = cyz & 1, cz = cyz >> 1;
                const float wyz = (cy ? ry : 1.0f - ry) * (cz ? rz : 1.0f - rz);
                const float w0 = wyz * (1.0f - rx);
                const float w1 = wyz * rx;

                unsigned i0, i1;
                if (hashed) {
                    unsigned gx = (unsigned)ix;
                    unsigned hyz = ((unsigned)(iy + cy) * 2654435761u) ^
                                   ((unsigned)(iz + cz) * 805459861u);
                    i0 = (gx ^ hyz) & (TBL - 1u);
                    i1 = ((gx + 1u) ^ hyz) & (TBL - 1u);
                } else {
                    int gy = min(max(iy + cy, 0), res - 1);
                    int gz = min(max(iz + cz, 0), res - 1);
                    int gx0 = min(max(ix, 0), res - 1);
                    int gx1 = min(max(ix + 1, 0), res - 1);
                    unsigned byz = (unsigned)(res * (gy + res * gz));
                    i0 = (unsigned)gx0 + byz;
                    i1 = (unsigned)gx1 + byz;
                }

                float2 f0, f1;
                if ((i0 ^ i1) == 1u) {
                    float4 v = __ldg((const float4*)(g + (i0 & ~1u)));
                    if (i0 & 1u) { f0 = make_float2(v.z, v.w); f1 = make_float2(v.x, v.y); }
                    else         { f0 = make_float2(v.x, v.y); f1 = make_float2(v.z, v.w); }
                } else {
                    f0 = __ldg(&g[i0]);
                    f1 = __ldg(&g[i1]);
                }
                a0 = fmaf(w0, f0.x, fmaf(w1, f1.x, a0));
                a1 = fmaf(w0, f0.y, fmaf(w1, f1.y, a1));
            }
            *(float2*)(act + erow * ASTRIDE + 2 * l) = make_float2(a0, a1);
        }
    } else {
#pragma unroll
        for (int li = 0; li < 8; li++)
            *(float2*)(act + erow * ASTRIDE + 2 * (lbase + li)) = make_float2(0.0f, 0.0f);
    }
    __syncthreads();   // point rows are written by two warps

    // ---- MLP: 8 warps, each owns 16 points (one m16 tile), all 64 outputs ----
    const int lane  = tid & 31;
    const int g     = lane >> 2;
    const int tig   = lane & 3;
    const int warp  = tid >> 5;
    const int mbase = warp * 16;

    float acc[8][4];

    layer_gemm<4>(act, g_w1p, mbase, g, tig, lane, acc);
    layer_store(act, mbase, g, tig, acc);
    __syncwarp();

    layer_gemm<8>(act, g_w2p, mbase, g, tig, lane, acc);
    layer_store(act, mbase, g, tig, acc);
    __syncwarp();

    layer_gemm<8>(act, g_w3p, mbase, g, tig, lane, acc);

    // ---- Output layer: sdf = softplus(h) . W4, reduce over tig quad ----
    float part[2] = {0.0f, 0.0f};
#pragma unroll
    for (int nt = 0; nt < 8; nt++) {
        const int j = nt * 8 + 2 * tig;
        float w4a = __ldg(&W4[j]);
        float w4b = __ldg(&W4[j + 1]);
        part[0] = fmaf(sp10(acc[nt][0]), w4a, fmaf(sp10(acc[nt][1]), w4b, part[0]));
        part[1] = fmaf(sp10(acc[nt][2]), w4a, fmaf(sp10(acc[nt][3]), w4b, part[1]));
    }
#pragma unroll
    for (int d = 0; d < 2; d++) {
        part[d] += __shfl_xor_sync(0xffffffffu, part[d], 1);
        part[d] += __shfl_xor_sync(0xffffffffu, part[d], 2);
    }
    if (tig == 0) {
        const int p0 = blockIdx.x * POINTS + mbase + g;
        if (p0 < N) out[p0] = part[0];
        if (p0 + 8 < N) out[p0 + 8] = part[1];
    }
}

extern "C" void kernel_launch(void* const* d_in, const int* in_sizes, int n_in,
                              void* d_out, int out_size)
{
    const float* x    = (const float*)d_in[0];
    const float* grid = (const float*)d_in[1];
    const float* W1   = (const float*)d_in[2];
    const float* W2   = (const float*)d_in[3];
    const float* W3   = (const float*)d_in[4];
    const float* W4   = (const float*)d_in[5];
    float* out = (float*)d_out;

    const int N = in_sizes[0] / 3;

    Meta meta;
    const double Bv = pow(2.0, log2(2048.0 / 16.0) / (double)(N_LEVELS - 1));
    unsigned mask = 0;
    for (int l = 0; l < N_LEVELS; l++) {
        double sc = 16.0 * pow(Bv, (double)l) - 1.0;
        int res = (int)ceil(sc) + 1;
        meta.scale[l] = (float)sc;
        meta.res[l] = res;
        if ((long long)res * res * res > (long long)TBL) mask |= (1u << l);
    }
    meta.hashed_mask = mask;

    prep_weights<<<16, 256>>>(W1, W2, W3);

    const int blocks = (N + POINTS - 1) / POINTS;
    sdf_kernel<<<blocks, NTHREADS>>>(x, grid, W4, out, N, meta);
}

// round 13
// speedup vs baseline: 1.6311x; 1.0467x over previous
#include <cuda_runtime.h>
#include <cuda_bf16.h>
#include <math.h>
#include <stdint.h>

#define N_LEVELS 16
#define TBL (1u << 19)
#define NTHREADS 256
#define POINTS 128
#define ASTRIDE 68   // 64 + 4 pad floats: conflict-free fragment access

struct Meta {
    float scale[N_LEVELS];
    int   res[N_LEVELS];
    unsigned hashed_mask;
};

// Fragment-packed single-tf32 weights: wp[(kt*8+nt)*32 + lane] = {w(k0,n), w(k1,n)}
// lane=(g<<2)|tig, k0=kt*8+tig, k1=k0+4, n=nt*8+g.  One coalesced LDG.64/fragment.
__device__ float2 g_w1p[4 * 8 * 32];
__device__ float2 g_w2p[8 * 8 * 32];
__device__ float2 g_w3p[8 * 8 * 32];

static __device__ __forceinline__ float tf32r(float x) {
    uint32_t r;
    asm("cvt.rna.tf32.f32 %0, %1;" : "=r"(r) : "f"(x));
    return __uint_as_float(r);
}

static __device__ __forceinline__ float sp10(float v) {
    float t = 10.0f * v;
    float e = __expf(-fabsf(t));
    return (__logf(1.0f + e) + fmaxf(t, 0.0f)) * 0.1f;
}

static __device__ __forceinline__ void mma8(float* d, const uint32_t* a,
                                            uint32_t b0, uint32_t b1) {
    asm volatile(
        "mma.sync.aligned.m16n8k8.row.col.f32.tf32.tf32.f32 "
        "{%0,%1,%2,%3}, {%4,%5,%6,%7}, {%8,%9}, {%0,%1,%2,%3};"
        : "+f"(d[0]), "+f"(d[1]), "+f"(d[2]), "+f"(d[3])
        : "r"(a[0]), "r"(a[1]), "r"(a[2]), "r"(a[3]), "r"(b0), "r"(b1));
}

template <int K>
static __device__ void pack_layer(const float* __restrict__ W, float2* __restrict__ wp,
                                  int tid, int stride) {
    const int KT = K / 8;
    for (int idx = tid; idx < KT * 8 * 32; idx += stride) {
        int kt = idx >> 8;
        int nt = (idx >> 5) & 7;
        int lane = idx & 31;
        int g = lane >> 2, tig = lane & 3;
        int k0 = kt * 8 + tig, k1 = k0 + 4;
        int n = nt * 8 + g;
        wp[idx] = make_float2(tf32r(W[n * K + k0]), tf32r(W[n * K + k1]));
    }
}

__global__ void prep_weights(const float* __restrict__ W1,
                             const float* __restrict__ W2,
                             const float* __restrict__ W3)
{
    const int tid = blockIdx.x * blockDim.x + threadIdx.x;
    const int stride = gridDim.x * blockDim.x;
    pack_layer<32>(W1, g_w1p, tid, stride);
    pack_layer<64>(W2, g_w2p, tid, stride);
    pack_layer<64>(W3, g_w3p, tid, stride);
}

// One layer GEMM: acc[8][4] += act[16pts x KT*8] @ W.  Warp-collective, m16 tile.
template <int KT>
static __device__ __forceinline__ void layer_gemm(const float* __restrict__ act,
                                                  const float2* __restrict__ wp,
                                                  int mbase, int g, int tig, int lane,
                                                  float acc[8][4])
{
#pragma unroll
    for (int nt = 0; nt < 8; nt++)
#pragma unroll
        for (int c = 0; c < 4; c++) acc[nt][c] = 0.0f;

#pragma unroll
    for (int kt = 0; kt < KT; kt++) {
        uint32_t ahi[4];
        const int r0 = mbase + g;
#pragma unroll
        for (int r = 0; r < 4; r++) {
            const int row = r0 + (r & 1) * 8;
            const int col = kt * 8 + tig + (r >> 1) * 4;
            ahi[r] = __float_as_uint(tf32r(act[row * ASTRIDE + col]));
        }
        const float2* wrow = wp + kt * 8 * 32 + lane;
#pragma unroll
        for (int nt = 0; nt < 8; nt++) {
            float2 w = __ldg(&wrow[nt * 32]);
            mma8(acc[nt], ahi, __float_as_uint(w.x), __float_as_uint(w.y));
        }
    }
}

static __device__ __forceinline__ void layer_store(float* __restrict__ act,
                                                   int mbase, int g, int tig,
                                                   const float acc[8][4])
{
    const int r0 = mbase + g;
#pragma unroll
    for (int nt = 0; nt < 8; nt++) {
        const int col = nt * 8 + 2 * tig;
        *(float2*)(act + r0 * ASTRIDE + col) =
            make_float2(sp10(acc[nt][0]), sp10(acc[nt][1]));
        *(float2*)(act + (r0 + 8) * ASTRIDE + col) =
            make_float2(sp10(acc[nt][2]), sp10(acc[nt][3]));
    }
}

__global__ void __launch_bounds__(NTHREADS, 4)
sdf_kernel(const float* __restrict__ x,
           const float* __restrict__ grid,
           const float* __restrict__ W4,
           float* __restrict__ out,
           int N, Meta meta)
{
    __shared__ float act[POINTS * ASTRIDE];

    const int tid = threadIdx.x;
    // Encoding: 2 threads per point; thread handles 8 levels.
    const int erow  = tid & (POINTS - 1);
    const int lbase = (tid >> 7) * 8;
    const int p = blockIdx.x * POINTS + erow;

    if (p < N) {
        const float px = x[p * 3 + 0];
        const float py = x[p * 3 + 1];
        const float pz = x[p * 3 + 2];

#pragma unroll 4
        for (int li = 0; li < 8; li++) {
            const int l = lbase + li;
            const float s = meta.scale[l];
            const int res = meta.res[l];
            const bool hashed = (meta.hashed_mask >> l) & 1u;

            float fx = fmaf(px, s, 0.5f);
            float fy = fmaf(py, s, 0.5f);
            float fz = fmaf(pz, s, 0.5f);
            float fx0 = floorf(fx), fy0 = floorf(fy), fz0 = floorf(fz);
            float rx = fx - fx0, ry = fy - fy0, rz = fz - fz0;
            int ix = (int)fx0, iy = (int)fy0, iz = (int)fz0;

            const float2* g = (const float2*)grid + (size_t)l * TBL;
            float a0 = 0.0f, a1 = 0.0f;

#pragma unroll
            for (int cyz = 0; cyz < 4; cyz++) {
                const int cy = cyz & 1, cz = cyz >> 1;
                const float wyz = (cy ? ry : 1.0f - ry) * (cz ? rz : 1.0f - rz);
                const float w0 = wyz * (1.0f - rx);
                const float w1 = wyz * rx;

                unsigned i0, i1;
                if (hashed) {
                    unsigned gx = (unsigned)ix;
                    unsigned hyz = ((unsigned)(iy + cy) * 2654435761u) ^
                                   ((unsigned)(iz + cz) * 805459861u);
                    i0 = (gx ^ hyz) & (TBL - 1u);
                    i1 = ((gx + 1u) ^ hyz) & (TBL - 1u);
                } else {
                    int gy = min(max(iy + cy, 0), res - 1);
                    int gz = min(max(iz + cz, 0), res - 1);
                    int gx0 = min(max(ix, 0), res - 1);
                    int gx1 = min(max(ix + 1, 0), res - 1);
                    unsigned byz = (unsigned)(res * (gy + res * gz));
                    i0 = (unsigned)gx0 + byz;
                    i1 = (unsigned)gx1 + byz;
                }

                float2 f0, f1;
                if ((i0 ^ i1) == 1u) {
                    float4 v = __ldg((const float4*)(g + (i0 & ~1u)));
                    if (i0 & 1u) { f0 = make_float2(v.z, v.w); f1 = make_float2(v.x, v.y); }
                    else         { f0 = make_float2(v.x, v.y); f1 = make_float2(v.z, v.w); }
                } else {
                    f0 = __ldg(&g[i0]);
                    f1 = __ldg(&g[i1]);
                }
                a0 = fmaf(w0, f0.x, fmaf(w1, f1.x, a0));
                a1 = fmaf(w0, f0.y, fmaf(w1, f1.y, a1));
            }
            *(float2*)(act + erow * ASTRIDE + 2 * l) = make_float2(a0, a1);
        }
    } else {
#pragma unroll
        for (int li = 0; li < 8; li++)
            *(float2*)(act + erow * ASTRIDE + 2 * (lbase + li)) = make_float2(0.0f, 0.0f);
    }
    __syncthreads();   // point rows are written by two warps

    // ---- MLP: 8 warps, each owns 16 points (one m16 tile), all 64 outputs ----
    const int lane  = tid & 31;
    const int g     = lane >> 2;
    const int tig   = lane & 3;
    const int warp  = tid >> 5;
    const int mbase = warp * 16;

    float acc[8][4];

    layer_gemm<4>(act, g_w1p, mbase, g, tig, lane, acc);
    layer_store(act, mbase, g, tig, acc);
    __syncwarp();

    layer_gemm<8>(act, g_w2p, mbase, g, tig, lane, acc);
    layer_store(act, mbase, g, tig, acc);
    __syncwarp();

    layer_gemm<8>(act, g_w3p, mbase, g, tig, lane, acc);

    // ---- Output layer: sdf = softplus(h) . W4, reduce over tig quad ----
    float part[2] = {0.0f, 0.0f};
#pragma unroll
    for (int nt = 0; nt < 8; nt++) {
        const int j = nt * 8 + 2 * tig;
        float w4a = __ldg(&W4[j]);
        float w4b = __ldg(&W4[j + 1]);
        part[0] = fmaf(sp10(acc[nt][0]), w4a, fmaf(sp10(acc[nt][1]), w4b, part[0]));
        part[1] = fmaf(sp10(acc[nt][2]), w4a, fmaf(sp10(acc[nt][3]), w4b, part[1]));
    }
#pragma unroll
    for (int d = 0; d < 2; d++) {
        part[d] += __shfl_xor_sync(0xffffffffu, part[d], 1);
        part[d] += __shfl_xor_sync(0xffffffffu, part[d], 2);
    }
    if (tig == 0) {
        const int p0 = blockIdx.x * POINTS + mbase + g;
        if (p0 < N) out[p0] = part[0];
        if (p0 + 8 < N) out[p0 + 8] = part[1];
    }
}

extern "C" void kernel_launch(void* const* d_in, const int* in_sizes, int n_in,
                              void* d_out, int out_size)
{
    const float* x    = (const float*)d_in[0];
    const float* grid = (const float*)d_in[1];
    const float* W1   = (const float*)d_in[2];
    const float* W2   = (const float*)d_in[3];
    const float* W3   = (const float*)d_in[4];
    const float* W4   = (const float*)d_in[5];
    float* out = (float*)d_out;

    const int N = in_sizes[0] / 3;

    Meta meta;
    const double Bv = pow(2.0, log2(2048.0 / 16.0) / (double)(N_LEVELS - 1));
    unsigned mask = 0;
    for (int l = 0; l < N_LEVELS; l++) {
        double sc = 16.0 * pow(Bv, (double)l) - 1.0;
        int res = (int)ceil(sc) + 1;
        meta.scale[l] = (float)sc;
        meta.res[l] = res;
        if ((long long)res * res * res > (long long)TBL) mask |= (1u << l);
    }
    meta.hashed_mask = mask;

    prep_weights<<<16, 256>>>(W1, W2, W3);

    const int blocks = (N + POINTS - 1) / POINTS;
    sdf_kernel<<<blocks, NTHREADS>>>(x, grid, W4, out, N, meta);
}

// round 15
// speedup vs baseline: 1.7665x; 1.0830x over previous
#include <cuda_runtime.h>
#include <cuda_bf16.h>
#include <math.h>
#include <stdint.h>

#define N_LEVELS 16
#define TBL (1u << 19)
#define NTHREADS 256
#define POINTS 128
#define ASTRIDE 72   // 64 + 8 pad floats: conflict-free float2 fragment loads

struct Meta {
    float scale[N_LEVELS];
    int   res[N_LEVELS];
    unsigned hashed_mask;
};

// Fragment-packed bf16 weights for mma.m16n8k16:
// wp[(kt*8+nt)*32 + lane] = uint2{ pack(w[k0],w[k0+1]), pack(w[k0+8],w[k0+9]) }
// lane=(g<<2)|tig, k0=kt*16+2*tig, n=nt*8+g.  One coalesced LDG.64 per fragment.
__device__ uint2 g_w1p[2 * 8 * 32];
__device__ uint2 g_w2p[4 * 8 * 32];
__device__ uint2 g_w3p[4 * 8 * 32];

static __device__ __forceinline__ float sp10(float v) {
    float t = 10.0f * v;
    float e = __expf(-fabsf(t));
    return (__logf(1.0f + e) + fmaxf(t, 0.0f)) * 0.1f;
}

// pack two floats as bf16x2 (lo = first/even-k element)
static __device__ __forceinline__ uint32_t bf16x2(float lo, float hi) {
    uint32_t r;
    asm("cvt.rn.bf16x2.f32 %0, %1, %2;" : "=r"(r) : "f"(hi), "f"(lo));
    return r;
}

// hi/lo split of a float2 (k-adjacent pair) into bf16x2 hi and bf16x2 lo
static __device__ __forceinline__ void split2(float2 a, uint32_t& hi, uint32_t& lo) {
    hi = bf16x2(a.x, a.y);
    float h0 = __uint_as_float(hi << 16);
    float h1 = __uint_as_float(hi & 0xffff0000u);
    lo = bf16x2(a.x - h0, a.y - h1);
}

static __device__ __forceinline__ void mma16(float* d, const uint32_t* a,
                                             uint32_t b0, uint32_t b1) {
    asm volatile(
        "mma.sync.aligned.m16n8k16.row.col.f32.bf16.bf16.f32 "
        "{%0,%1,%2,%3}, {%4,%5,%6,%7}, {%8,%9}, {%0,%1,%2,%3};"
        : "+f"(d[0]), "+f"(d[1]), "+f"(d[2]), "+f"(d[3])
        : "r"(a[0]), "r"(a[1]), "r"(a[2]), "r"(a[3]), "r"(b0), "r"(b1));
}

static __device__ __forceinline__ uint32_t packw(float a, float b) {
    uint32_t la = (uint32_t)__bfloat16_as_ushort(__float2bfloat16_rn(a));
    uint32_t lb = (uint32_t)__bfloat16_as_ushort(__float2bfloat16_rn(b));
    return la | (lb << 16);
}

template <int K>
static __device__ void pack_layer(const float* __restrict__ W, uint2* __restrict__ wp,
                                  int tid, int stride) {
    const int KT = K / 16;
    for (int idx = tid; idx < KT * 8 * 32; idx += stride) {
        int kt = idx >> 8;
        int nt = (idx >> 5) & 7;
        int lane = idx & 31;
        int g = lane >> 2, tig = lane & 3;
        int k0 = kt * 16 + 2 * tig;
        int n = nt * 8 + g;
        uint2 v;
        v.x = packw(W[n * K + k0],     W[n * K + k0 + 1]);
        v.y = packw(W[n * K + k0 + 8], W[n * K + k0 + 9]);
        wp[idx] = v;
    }
}

__global__ void prep_weights(const float* __restrict__ W1,
                             const float* __restrict__ W2,
                             const float* __restrict__ W3)
{
    const int tid = blockIdx.x * blockDim.x + threadIdx.x;
    const int stride = gridDim.x * blockDim.x;
    pack_layer<32>(W1, g_w1p, tid, stride);
    pack_layer<64>(W2, g_w2p, tid, stride);
    pack_layer<64>(W3, g_w3p, tid, stride);
}

// One layer GEMM: acc[8][4] += act[16pts x KT16*16] @ W.  Warp-collective m16 tile.
// Act-side hi/lo bf16 compensation: 2 MMAs per fragment.
template <int KT16>
static __device__ __forceinline__ void layer_gemm(const float* __restrict__ act,
                                                  const uint2* __restrict__ wp,
                                                  int mbase, int g, int tig, int lane,
                                                  float acc[8][4])
{
#pragma unroll
    for (int nt = 0; nt < 8; nt++)
#pragma unroll
        for (int c = 0; c < 4; c++) acc[nt][c] = 0.0f;

#pragma unroll
    for (int kt = 0; kt < KT16; kt++) {
        const int kb = kt * 16;
        const int r0 = mbase + g;
        float2 q0 = *(const float2*)(act + r0 * ASTRIDE + kb + 2 * tig);
        float2 q1 = *(const float2*)(act + (r0 + 8) * ASTRIDE + kb + 2 * tig);
        float2 q2 = *(const float2*)(act + r0 * ASTRIDE + kb + 8 + 2 * tig);
        float2 q3 = *(const float2*)(act + (r0 + 8) * ASTRIDE + kb + 8 + 2 * tig);

        uint32_t ahi[4], alo[4];
        split2(q0, ahi[0], alo[0]);
        split2(q1, ahi[1], alo[1]);
        split2(q2, ahi[2], alo[2]);
        split2(q3, ahi[3], alo[3]);

        const uint2* wrow = wp + kt * 8 * 32 + lane;
#pragma unroll
        for (int nt = 0; nt < 8; nt++) {
            uint2 w = __ldg(&wrow[nt * 32]);
            mma16(acc[nt], ahi, w.x, w.y);
            mma16(acc[nt], alo, w.x, w.y);
        }
    }
}

static __device__ __forceinline__ void layer_store(float* __restrict__ act,
                                                   int mbase, int g, int tig,
                                                   const float acc[8][4])
{
    const int r0 = mbase + g;
#pragma unroll
    for (int nt = 0; nt < 8; nt++) {
        const int col = nt * 8 + 2 * tig;
        *(float2*)(act + r0 * ASTRIDE + col) =
            make_float2(sp10(acc[nt][0]), sp10(acc[nt][1]));
        *(float2*)(act + (r0 + 8) * ASTRIDE + col) =
            make_float2(sp10(acc[nt][2]), sp10(acc[nt][3]));
    }
}

__global__ void __launch_bounds__(NTHREADS, 4)
sdf_kernel(const float* __restrict__ x,
           const float* __restrict__ grid,
           const float* __restrict__ W4,
           float* __restrict__ out,
           int N, Meta meta)
{
    __shared__ float act[POINTS * ASTRIDE];

    const int tid = threadIdx.x;
    // Encoding: 2 threads per point; thread handles 8 levels.
    const int erow  = tid & (POINTS - 1);
    const int lbase = (tid >> 7) * 8;
    const int p = blockIdx.x * POINTS + erow;

    if (p < N) {
        const float px = x[p * 3 + 0];
        const float py = x[p * 3 + 1];
        const float pz = x[p * 3 + 2];

#pragma unroll 4
        for (int li = 0; li < 8; li++) {
            const int l = lbase + li;
            const float s = meta.scale[l];
            const int res = meta.res[l];
            const bool hashed = (meta.hashed_mask >> l) & 1u;

            float fx = fmaf(px, s, 0.5f);
            float fy = fmaf(py, s, 0.5f);
            float fz = fmaf(pz, s, 0.5f);
            float fx0 = floorf(fx), fy0 = floorf(fy), fz0 = floorf(fz);
            float rx = fx - fx0, ry = fy - fy0, rz = fz - fz0;
            int ix = (int)fx0, iy = (int)fy0, iz = (int)fz0;

            const float2* g = (const float2*)grid + (size_t)l * TBL;
            float a0 = 0.0f, a1 = 0.0f;

            // hoisted per-level index precompute
            unsigned hy0, hy1, hz0, hz1, gxu = (unsigned)ix;
            unsigned dgy0, dgy1, dgz0, dgz1, dgx0, dgx1;
            if (hashed) {
                hy0 = (unsigned)iy * 2654435761u;  hy1 = hy0 + 2654435761u;
                hz0 = (unsigned)iz * 805459861u;   hz1 = hz0 + 805459861u;
            } else {
                dgy0 = (unsigned)min(max(iy, 0), res - 1);
                dgy1 = (unsigned)min(max(iy + 1, 0), res - 1);
                dgz0 = (unsigned)min(max(iz, 0), res - 1);
                dgz1 = (unsigned)min(max(iz + 1, 0), res - 1);
                dgx0 = (unsigned)min(max(ix, 0), res - 1);
                dgx1 = (unsigned)min(max(ix + 1, 0), res - 1);
            }

#pragma unroll
            for (int cyz = 0; cyz < 4; cyz++) {
                const int cy = cyz & 1, cz = cyz >> 1;
                const float wyz = (cy ? ry : 1.0f - ry) * (cz ? rz : 1.0f - rz);
                const float w0 = wyz * (1.0f - rx);
                const float w1 = wyz * rx;

                unsigned i0, i1;
                if (hashed) {
                    unsigned hyz = (cy ? hy1 : hy0) ^ (cz ? hz1 : hz0);
                    i0 = (gxu ^ hyz) & (TBL - 1u);
                    i1 = ((gxu + 1u) ^ hyz) & (TBL - 1u);
                } else {
                    unsigned byz = (unsigned)res * ((cy ? dgy1 : dgy0) +
                                   (unsigned)res * (cz ? dgz1 : dgz0));
                    i0 = dgx0 + byz;
                    i1 = dgx1 + byz;
                }

                float2 f0, f1;
                if ((i0 ^ i1) == 1u) {
                    float4 v = __ldg((const float4*)(g + (i0 & ~1u)));
                    if (i0 & 1u) { f0 = make_float2(v.z, v.w); f1 = make_float2(v.x, v.y); }
                    else         { f0 = make_float2(v.x, v.y); f1 = make_float2(v.z, v.w); }
                } else {
                    f0 = __ldg(&g[i0]);
                    f1 = __ldg(&g[i1]);
                }
                a0 = fmaf(w0, f0.x, fmaf(w1, f1.x, a0));
                a1 = fmaf(w0, f0.y, fmaf(w1, f1.y, a1));
            }
            *(float2*)(act + erow * ASTRIDE + 2 * l) = make_float2(a0, a1);
        }
    } else {
#pragma unroll
        for (int li = 0; li < 8; li++)
            *(float2*)(act + erow * ASTRIDE + 2 * (lbase + li)) = make_float2(0.0f, 0.0f);
    }
    __syncthreads();   // point rows are written by two warps

    // ---- MLP: 8 warps, each owns 16 points (one m16 tile), all 64 outputs ----
    const int lane  = tid & 31;
    const int g     = lane >> 2;
    const int tig   = lane & 3;
    const int warp  = tid >> 5;
    const int mbase = warp * 16;

    float acc[8][4];

    layer_gemm<2>(act, g_w1p, mbase, g, tig, lane, acc);   // K=32
    layer_store(act, mbase, g, tig, acc);
    __syncwarp();

    layer_gemm<4>(act, g_w2p, mbase, g, tig, lane, acc);   // K=64
    layer_store(act, mbase, g, tig, acc);
    __syncwarp();

    layer_gemm<4>(act, g_w3p, mbase, g, tig, lane, acc);   // K=64

    // ---- Output layer: sdf = softplus(h) . W4, reduce over tig quad ----
    float part[2] = {0.0f, 0.0f};
#pragma unroll
    for (int nt = 0; nt < 8; nt++) {
        const int j = nt * 8 + 2 * tig;
        float w4a = __ldg(&W4[j]);
        float w4b = __ldg(&W4[j + 1]);
        part[0] = fmaf(sp10(acc[nt][0]), w4a, fmaf(sp10(acc[nt][1]), w4b, part[0]));
        part[1] = fmaf(sp10(acc[nt][2]), w4a, fmaf(sp10(acc[nt][3]), w4b, part[1]));
    }
#pragma unroll
    for (int d = 0; d < 2; d++) {
        part[d] += __shfl_xor_sync(0xffffffffu, part[d], 1);
        part[d] += __shfl_xor_sync(0xffffffffu, part[d], 2);
    }
    if (tig == 0) {
        const int p0 = blockIdx.x * POINTS + mbase + g;
        if (p0 < N) out[p0] = part[0];
        if (p0 + 8 < N) out[p0 + 8] = part[1];
    }
}

extern "C" void kernel_launch(void* const* d_in, const int* in_sizes, int n_in,
                              void* d_out, int out_size)
{
    const float* x    = (const float*)d_in[0];
    const float* grid = (const float*)d_in[1];
    const float* W1   = (const float*)d_in[2];
    const float* W2   = (const float*)d_in[3];
    const float* W3   = (const float*)d_in[4];
    const float* W4   = (const float*)d_in[5];
    float* out = (float*)d_out;

    const int N = in_sizes[0] / 3;

    Meta meta;
    const double Bv = pow(2.0, log2(2048.0 / 16.0) / (double)(N_LEVELS - 1));
    unsigned mask = 0;
    for (int l = 0; l < N_LEVELS; l++) {
        double sc = 16.0 * pow(Bv, (double)l) - 1.0;
        int res = (int)ceil(sc) + 1;
        meta.scale[l] = (float)sc;
        meta.res[l] = res;
        if ((long long)res * res * res > (long long)TBL) mask |= (1u << l);
    }
    meta.hashed_mask = mask;

    prep_weights<<<16, 256>>>(W1, W2, W3);

    const int blocks = (N + POINTS - 1) / POINTS;
    sdf_kernel<<<blocks, NTHREADS>>>(x, grid, W4, out, N, meta);
}